// round 14
// baseline (speedup 1.0000x reference)
#include <cuda_runtime.h>
#include <stdint.h>

// ---------------------------------------------------------------------------
// DynamicFixedQuantizer (bits=8, sigma0=0.25, r_max=0.01):
//   overflow  = (#x > t_max   + #x < t_min  ) / n      (t_max=31.75, t_min=-32)
//   underflow = (#x > t_max/2 + #x < t_min/2) / n
//   sigma = ov > 0.01 ? 2*sigma : (uf < 0.01 ? sigma/2 : sigma)
//   out = clip(floor(x/sigma + U[0,1))*sigma, -128*sigma, 127*sigma)
//
// RNG (bit-exact JAX threefry2x32, partitionable mode — default since 0.4.30):
//   counts1, counts2 = hi/lo words of 64-bit iota  -> (0, i) for n < 2^32
//   bits1, bits2     = threefry2x32(key, counts1, counts2)
//   bits(i)          = bits1 ^ bits2              <-- XOR fold for 32-bit width
//   key = fold_in(key(42), 0) = threefry2x32(key=(0,42), count=(0,0))
//   uniform = bitcast((bits >> 9) | 0x3f800000) - 1.0
// ---------------------------------------------------------------------------

__device__ unsigned int g_cnt[2];   // [0]=overflow count, [1]=underflow count

// ---------------- threefry-2x32 device helpers ------------------------------
__device__ __forceinline__ void tf_round(uint32_t& a, uint32_t& b, int r) {
    a += b;
    b = __funnelshift_l(b, b, r);   // rotl32 in one SHF
    b ^= a;
}

// Full 20-round threefry with x0_in = 0, x1_in = i; returns w0 ^ w1.
__device__ __forceinline__ uint32_t threefry_xor(uint32_t k0, uint32_t k1,
                                                 uint32_t k2, uint32_t i) {
    uint32_t x0 = k0;          // 0 + k0
    uint32_t x1 = i + k1;
    tf_round(x0, x1, 13); tf_round(x0, x1, 15); tf_round(x0, x1, 26); tf_round(x0, x1, 6);
    x0 += k1; x1 += k2 + 1u;
    tf_round(x0, x1, 17); tf_round(x0, x1, 29); tf_round(x0, x1, 16); tf_round(x0, x1, 24);
    x0 += k2; x1 += k0 + 2u;
    tf_round(x0, x1, 13); tf_round(x0, x1, 15); tf_round(x0, x1, 26); tf_round(x0, x1, 6);
    x0 += k0; x1 += k1 + 3u;
    tf_round(x0, x1, 17); tf_round(x0, x1, 29); tf_round(x0, x1, 16); tf_round(x0, x1, 24);
    x0 += k1; x1 += k2 + 4u;
    tf_round(x0, x1, 13); tf_round(x0, x1, 15); tf_round(x0, x1, 26); tf_round(x0, x1, 6);
    x0 += k2;                  // word0 final injection (live: needed for xor)
    x1 += k0 + 5u;             // word1 final injection
    return x0 ^ x1;
}

// ---------------- kernels ----------------------------------------------------
__global__ void dfq_zero_kernel() {
    g_cnt[0] = 0u;
    g_cnt[1] = 0u;
}

__global__ void __launch_bounds__(256)
dfq_count_kernel(const float* __restrict__ x, int n4) {
    const float4* __restrict__ x4 = (const float4*)x;
    const float TMAX = 31.75f, TMIN = -32.0f;     // sigma0 = 0.25
    const float HMAX = 15.875f, HMIN = -16.0f;    // 0.5*t_max, 0.5*t_min
    unsigned int ov = 0u, uf = 0u;
    const int stride = gridDim.x * blockDim.x;
    for (int i = blockIdx.x * blockDim.x + threadIdx.x; i < n4; i += stride) {
        float4 v = __ldg(x4 + i);
        ov += (unsigned)(v.x > TMAX) + (unsigned)(v.x < TMIN)
            + (unsigned)(v.y > TMAX) + (unsigned)(v.y < TMIN)
            + (unsigned)(v.z > TMAX) + (unsigned)(v.z < TMIN)
            + (unsigned)(v.w > TMAX) + (unsigned)(v.w < TMIN);
        uf += (unsigned)(v.x > HMAX) + (unsigned)(v.x < HMIN)
            + (unsigned)(v.y > HMAX) + (unsigned)(v.y < HMIN)
            + (unsigned)(v.z > HMAX) + (unsigned)(v.z < HMIN)
            + (unsigned)(v.w > HMAX) + (unsigned)(v.w < HMIN);
    }
    #pragma unroll
    for (int o = 16; o > 0; o >>= 1) {
        ov += __shfl_down_sync(0xffffffffu, ov, o);
        uf += __shfl_down_sync(0xffffffffu, uf, o);
    }
    __shared__ unsigned int s_ov[8], s_uf[8];
    const int w = threadIdx.x >> 5;
    if ((threadIdx.x & 31) == 0) { s_ov[w] = ov; s_uf[w] = uf; }
    __syncthreads();
    if (threadIdx.x == 0) {
        unsigned int a = 0u, b = 0u;
        #pragma unroll
        for (int i = 0; i < 8; i++) { a += s_ov[i]; b += s_uf[i]; }
        atomicAdd(&g_cnt[0], a);
        atomicAdd(&g_cnt[1], b);
    }
}

__device__ __forceinline__ float dfq_quant1(float v, uint32_t bits,
                                            float inv_sigma, float sigma,
                                            float t_min, float t_max) {
    // JAX uniform: bitcast((bits >> 9) | 0x3f800000) - 1.0 in [0,1)
    float u = __uint_as_float((bits >> 9) | 0x3f800000u) - 1.0f;
    // sigma is a power of two: v*inv_sigma == v/sigma bit-exactly, and FFMA
    // contraction of (v*inv_sigma + u) rounds identically (product exact).
    float t = floorf(v * inv_sigma + u);
    float q = t * sigma;                          // exact power-of-two scale
    return fminf(fmaxf(q, t_min), t_max);
}

// Grid-strided over float4 chunks: each thread handles ITERS chunks so the
// per-thread sigma-decision overhead amortizes over 16 elements.
__global__ void __launch_bounds__(256)
dfq_quant_kernel(const float* __restrict__ x, float* __restrict__ out,
                 uint32_t k0, uint32_t k1, unsigned int n4, float nf) {
    // sigma decision from global counts (uniform value, L2-broadcast loads)
    const float ov = __uint2float_rn(g_cnt[0]) / nf;
    const float uf = __uint2float_rn(g_cnt[1]) / nf;
    float sigma = 0.25f;
    if (ov > 0.01f)      sigma = 0.5f;
    else if (uf < 0.01f) sigma = 0.125f;
    const float t_max     = sigma * 128.0f - sigma;
    const float t_min     = -(sigma * 128.0f);
    const float inv_sigma = 1.0f / sigma;
    const uint32_t k2 = k0 ^ k1 ^ 0x1BD11BDAu;

    const unsigned int stride = gridDim.x * blockDim.x;
    for (unsigned int c = blockIdx.x * blockDim.x + threadIdx.x; c < n4; c += stride) {
        const unsigned int base = c * 4u;
        float4 a = __ldg((const float4*)(x) + c);

        // 4 independent 20-round hash chains for ILP
        uint32_t b0 = threefry_xor(k0, k1, k2, base + 0u);
        uint32_t b1 = threefry_xor(k0, k1, k2, base + 1u);
        uint32_t b2 = threefry_xor(k0, k1, k2, base + 2u);
        uint32_t b3 = threefry_xor(k0, k1, k2, base + 3u);

        float4 q;
        q.x = dfq_quant1(a.x, b0, inv_sigma, sigma, t_min, t_max);
        q.y = dfq_quant1(a.y, b1, inv_sigma, sigma, t_min, t_max);
        q.z = dfq_quant1(a.z, b2, inv_sigma, sigma, t_min, t_max);
        q.w = dfq_quant1(a.w, b3, inv_sigma, sigma, t_min, t_max);

        ((float4*)out)[c] = q;
    }
}

// ---------------- host-side threefry (folded key, computed once) -----------
static inline uint32_t h_rotl(uint32_t v, int r) { return (v << r) | (v >> (32 - r)); }
static void host_threefry2x32(uint32_t k0, uint32_t k1, uint32_t& x0, uint32_t& x1) {
    const uint32_t k2 = k0 ^ k1 ^ 0x1BD11BDAu;
    const int rotA[4] = {13, 15, 26, 6};
    const int rotB[4] = {17, 29, 16, 24};
    x0 += k0; x1 += k1;
    for (int i = 0; i < 4; i++) { x0 += x1; x1 = h_rotl(x1, rotA[i]); x1 ^= x0; }
    x0 += k1; x1 += k2 + 1u;
    for (int i = 0; i < 4; i++) { x0 += x1; x1 = h_rotl(x1, rotB[i]); x1 ^= x0; }
    x0 += k2; x1 += k0 + 2u;
    for (int i = 0; i < 4; i++) { x0 += x1; x1 = h_rotl(x1, rotA[i]); x1 ^= x0; }
    x0 += k0; x1 += k1 + 3u;
    for (int i = 0; i < 4; i++) { x0 += x1; x1 = h_rotl(x1, rotB[i]); x1 ^= x0; }
    x0 += k1; x1 += k2 + 4u;
    for (int i = 0; i < 4; i++) { x0 += x1; x1 = h_rotl(x1, rotA[i]); x1 ^= x0; }
    x0 += k2; x1 += k0 + 5u;
}

extern "C" void kernel_launch(void* const* d_in, const int* in_sizes, int n_in,
                              void* d_out, int out_size) {
    const float* x = (const float*)d_in[0];
    float* out = (float*)d_out;
    const unsigned int n = (unsigned int)in_sizes[0];   // 32*2048*2048 = 2^27

    // folded key = fold_in(key(42), 0) = threefry2x32(key=(0,42), count=(0,0))
    uint32_t fk0 = 0u, fk1 = 0u;
    host_threefry2x32(0u, 42u, fk0, fk1);

    dfq_zero_kernel<<<1, 1>>>();

    const unsigned int n4 = n / 4u;
    dfq_count_kernel<<<2368, 256>>>(x, (int)n4);        // 16 blocks/SM grid-stride

    // 4 float4 iterations per thread (16 elems/thread) to amortize overhead
    unsigned int qThreads = (n4 + 3u) / 4u;
    unsigned int qBlocks  = (qThreads + 255u) / 256u;
    dfq_quant_kernel<<<qBlocks, 256>>>(x, out, fk0, fk1, n4, (float)n);
}

// round 15
// speedup vs baseline: 1.0018x; 1.0018x over previous
#include <cuda_runtime.h>
#include <stdint.h>

// ---------------------------------------------------------------------------
// DynamicFixedQuantizer (bits=8, sigma0=0.25, r_max=0.01):
//   overflow  = (#x > t_max   + #x < t_min  ) / n      (t_max=31.75, t_min=-32)
//   underflow = (#x > t_max/2 + #x < t_min/2) / n
//   sigma = ov > 0.01 ? 2*sigma : (uf < 0.01 ? sigma/2 : sigma)
//   out = clip(floor(x/sigma + U[0,1))*sigma, -128*sigma, 127*sigma)
//
// RNG (bit-exact JAX threefry2x32, partitionable mode — default since 0.4.30):
//   counts1, counts2 = hi/lo words of 64-bit iota  -> (0, i) for n < 2^32
//   bits1, bits2     = threefry2x32(key, counts1, counts2)
//   bits(i)          = bits1 ^ bits2              <-- XOR fold for 32-bit width
//   key = fold_in(key(42), 0) = threefry2x32(key=(0,42), count=(0,0))
//   uniform = bitcast((bits >> 9) | 0x3f800000) - 1.0
// ---------------------------------------------------------------------------

__device__ unsigned int g_cnt[2];   // [0]=overflow count, [1]=underflow count

// ---------------- threefry-2x32 device helpers ------------------------------
__device__ __forceinline__ void tf_round(uint32_t& a, uint32_t& b, int r) {
    a += b;
    b = __funnelshift_l(b, b, r);   // rotl32 in one SHF
    b ^= a;
}

// Full 20-round threefry with x0_in = 0, x1_in = i; returns w0 ^ w1.
__device__ __forceinline__ uint32_t threefry_xor(uint32_t k0, uint32_t k1,
                                                 uint32_t k2, uint32_t i) {
    uint32_t x0 = k0;          // 0 + k0
    uint32_t x1 = i + k1;
    tf_round(x0, x1, 13); tf_round(x0, x1, 15); tf_round(x0, x1, 26); tf_round(x0, x1, 6);
    x0 += k1; x1 += k2 + 1u;
    tf_round(x0, x1, 17); tf_round(x0, x1, 29); tf_round(x0, x1, 16); tf_round(x0, x1, 24);
    x0 += k2; x1 += k0 + 2u;
    tf_round(x0, x1, 13); tf_round(x0, x1, 15); tf_round(x0, x1, 26); tf_round(x0, x1, 6);
    x0 += k0; x1 += k1 + 3u;
    tf_round(x0, x1, 17); tf_round(x0, x1, 29); tf_round(x0, x1, 16); tf_round(x0, x1, 24);
    x0 += k1; x1 += k2 + 4u;
    tf_round(x0, x1, 13); tf_round(x0, x1, 15); tf_round(x0, x1, 26); tf_round(x0, x1, 6);
    x0 += k2;                  // word0 final injection (live: needed for xor)
    x1 += k0 + 5u;             // word1 final injection
    return x0 ^ x1;
}

// ---------------- kernels ----------------------------------------------------
__global__ void dfq_zero_kernel() {
    g_cnt[0] = 0u;
    g_cnt[1] = 0u;
}

__global__ void __launch_bounds__(256)
dfq_count_kernel(const float* __restrict__ x, int n4) {
    const float4* __restrict__ x4 = (const float4*)x;
    const float TMAX = 31.75f, TMIN = -32.0f;     // sigma0 = 0.25
    const float HMAX = 15.875f, HMIN = -16.0f;    // 0.5*t_max, 0.5*t_min
    unsigned int ov = 0u, uf = 0u;
    const int stride = gridDim.x * blockDim.x;
    for (int i = blockIdx.x * blockDim.x + threadIdx.x; i < n4; i += stride) {
        float4 v = __ldg(x4 + i);
        ov += (unsigned)(v.x > TMAX) + (unsigned)(v.x < TMIN)
            + (unsigned)(v.y > TMAX) + (unsigned)(v.y < TMIN)
            + (unsigned)(v.z > TMAX) + (unsigned)(v.z < TMIN)
            + (unsigned)(v.w > TMAX) + (unsigned)(v.w < TMIN);
        uf += (unsigned)(v.x > HMAX) + (unsigned)(v.x < HMIN)
            + (unsigned)(v.y > HMAX) + (unsigned)(v.y < HMIN)
            + (unsigned)(v.z > HMAX) + (unsigned)(v.z < HMIN)
            + (unsigned)(v.w > HMAX) + (unsigned)(v.w < HMIN);
    }
    #pragma unroll
    for (int o = 16; o > 0; o >>= 1) {
        ov += __shfl_down_sync(0xffffffffu, ov, o);
        uf += __shfl_down_sync(0xffffffffu, uf, o);
    }
    __shared__ unsigned int s_ov[8], s_uf[8];
    const int w = threadIdx.x >> 5;
    if ((threadIdx.x & 31) == 0) { s_ov[w] = ov; s_uf[w] = uf; }
    __syncthreads();
    if (threadIdx.x == 0) {
        unsigned int a = 0u, b = 0u;
        #pragma unroll
        for (int i = 0; i < 8; i++) { a += s_ov[i]; b += s_uf[i]; }
        atomicAdd(&g_cnt[0], a);
        atomicAdd(&g_cnt[1], b);
    }
}

__device__ __forceinline__ float dfq_quant1(float v, uint32_t bits,
                                            float inv_sigma, float sigma,
                                            float t_min, float t_max) {
    // JAX uniform: bitcast((bits >> 9) | 0x3f800000) - 1.0 in [0,1)
    float u = __uint_as_float((bits >> 9) | 0x3f800000u) - 1.0f;
    // sigma is a power of two: v*inv_sigma == v/sigma bit-exactly, and FFMA
    // contraction of (v*inv_sigma + u) rounds identically (product exact).
    float t = floorf(v * inv_sigma + u);
    float q = t * sigma;                          // exact power-of-two scale
    return fminf(fmaxf(q, t_min), t_max);
}

// Grid-strided over float4 chunks: each thread handles ITERS chunks so the
// per-thread sigma-decision overhead amortizes over 16 elements.
__global__ void __launch_bounds__(256)
dfq_quant_kernel(const float* __restrict__ x, float* __restrict__ out,
                 uint32_t k0, uint32_t k1, unsigned int n4, float nf) {
    // sigma decision from global counts (uniform value, L2-broadcast loads)
    const float ov = __uint2float_rn(g_cnt[0]) / nf;
    const float uf = __uint2float_rn(g_cnt[1]) / nf;
    float sigma = 0.25f;
    if (ov > 0.01f)      sigma = 0.5f;
    else if (uf < 0.01f) sigma = 0.125f;
    const float t_max     = sigma * 128.0f - sigma;
    const float t_min     = -(sigma * 128.0f);
    const float inv_sigma = 1.0f / sigma;
    const uint32_t k2 = k0 ^ k1 ^ 0x1BD11BDAu;

    const unsigned int stride = gridDim.x * blockDim.x;
    for (unsigned int c = blockIdx.x * blockDim.x + threadIdx.x; c < n4; c += stride) {
        const unsigned int base = c * 4u;
        float4 a = __ldg((const float4*)(x) + c);

        // 4 independent 20-round hash chains for ILP
        uint32_t b0 = threefry_xor(k0, k1, k2, base + 0u);
        uint32_t b1 = threefry_xor(k0, k1, k2, base + 1u);
        uint32_t b2 = threefry_xor(k0, k1, k2, base + 2u);
        uint32_t b3 = threefry_xor(k0, k1, k2, base + 3u);

        float4 q;
        q.x = dfq_quant1(a.x, b0, inv_sigma, sigma, t_min, t_max);
        q.y = dfq_quant1(a.y, b1, inv_sigma, sigma, t_min, t_max);
        q.z = dfq_quant1(a.z, b2, inv_sigma, sigma, t_min, t_max);
        q.w = dfq_quant1(a.w, b3, inv_sigma, sigma, t_min, t_max);

        ((float4*)out)[c] = q;
    }
}

// ---------------- host-side threefry (folded key, computed once) -----------
static inline uint32_t h_rotl(uint32_t v, int r) { return (v << r) | (v >> (32 - r)); }
static void host_threefry2x32(uint32_t k0, uint32_t k1, uint32_t& x0, uint32_t& x1) {
    const uint32_t k2 = k0 ^ k1 ^ 0x1BD11BDAu;
    const int rotA[4] = {13, 15, 26, 6};
    const int rotB[4] = {17, 29, 16, 24};
    x0 += k0; x1 += k1;
    for (int i = 0; i < 4; i++) { x0 += x1; x1 = h_rotl(x1, rotA[i]); x1 ^= x0; }
    x0 += k1; x1 += k2 + 1u;
    for (int i = 0; i < 4; i++) { x0 += x1; x1 = h_rotl(x1, rotB[i]); x1 ^= x0; }
    x0 += k2; x1 += k0 + 2u;
    for (int i = 0; i < 4; i++) { x0 += x1; x1 = h_rotl(x1, rotA[i]); x1 ^= x0; }
    x0 += k0; x1 += k1 + 3u;
    for (int i = 0; i < 4; i++) { x0 += x1; x1 = h_rotl(x1, rotB[i]); x1 ^= x0; }
    x0 += k1; x1 += k2 + 4u;
    for (int i = 0; i < 4; i++) { x0 += x1; x1 = h_rotl(x1, rotA[i]); x1 ^= x0; }
    x0 += k2; x1 += k0 + 5u;
}

extern "C" void kernel_launch(void* const* d_in, const int* in_sizes, int n_in,
                              void* d_out, int out_size) {
    const float* x = (const float*)d_in[0];
    float* out = (float*)d_out;
    const unsigned int n = (unsigned int)in_sizes[0];   // 32*2048*2048 = 2^27

    // folded key = fold_in(key(42), 0) = threefry2x32(key=(0,42), count=(0,0))
    uint32_t fk0 = 0u, fk1 = 0u;
    host_threefry2x32(0u, 42u, fk0, fk1);

    dfq_zero_kernel<<<1, 1>>>();

    const unsigned int n4 = n / 4u;
    dfq_count_kernel<<<2368, 256>>>(x, (int)n4);        // 16 blocks/SM grid-stride

    // 4 float4 iterations per thread (16 elems/thread) to amortize overhead
    unsigned int qThreads = (n4 + 3u) / 4u;
    unsigned int qBlocks  = (qThreads + 255u) / 256u;
    dfq_quant_kernel<<<qBlocks, 256>>>(x, out, fk0, fk1, n4, (float)n);
}